// round 16
// baseline (speedup 1.0000x reference)
#include <cuda_runtime.h>
#include <cuda_bf16.h>
#include <math.h>
#include <stdint.h>

#define SBH 128
#define SN  3136
#define SM  196
#define SMP 224                    /* k1 row stride (bf16), 32-aligned, zero-padded */
#define SHW 56
#define QS  0.35355339059327379f   /* 64^-0.25 */
#define NSP 256
#define NSE ((size_t)(NSP*NSP))

// ---------------- scratch (static device globals; no allocation) ----------------
__device__ float g_Ql [SBH*SM*64];
__device__ float g_ql2[SBH*SM];
__device__ float g_qn2[SBH*SN];
__device__ __align__(16) __nv_bfloat16 g_k1[(size_t)SBH*SN*SMP];   // 180 MB bf16
__device__ float g_P  [SBH*SM*SM];
__device__ float g_nsc[SBH];
__device__ __align__(16) __nv_bfloat16 g_Pb[SBH*NSE];   // bf16 P, padded 256x256
__device__ __align__(16) __nv_bfloat16 g_Ea[SBH*NSE];   // E ping
__device__ __align__(16) __nv_bfloat16 g_Eb[SBH*NSE];   // E pong
__device__ __align__(16) float g_y0[SBH*256*64];        // y ping (fp32)
__device__ __align__(16) float g_y1[SBH*256*64];        // y pong

// ================= helpers =================
__device__ __forceinline__ uint32_t pack2(__nv_bfloat16 a, __nv_bfloat16 b) {
  return (uint32_t)__bfloat16_as_ushort(a) | ((uint32_t)__bfloat16_as_ushort(b) << 16);
}
__device__ __forceinline__ void mma16816(float* c, const uint32_t* a, const uint32_t* b) {
  asm volatile(
    "mma.sync.aligned.m16n8k16.row.col.f32.bf16.bf16.f32 "
    "{%0,%1,%2,%3}, {%4,%5,%6,%7}, {%8,%9}, {%0,%1,%2,%3};"
    : "+f"(c[0]), "+f"(c[1]), "+f"(c[2]), "+f"(c[3])
    : "r"(a[0]), "r"(a[1]), "r"(a[2]), "r"(a[3]), "r"(b[0]), "r"(b[1]));
}
__device__ __forceinline__ uint32_t cvt_tf32(float x) {
  uint32_t r; asm("cvt.rna.tf32.f32 %0, %1;" : "=r"(r) : "f"(x)); return r;
}
__device__ __forceinline__ void mma_tf32(float* c, const uint32_t* a, const uint32_t* b) {
  asm volatile(
    "mma.sync.aligned.m16n8k8.row.col.f32.tf32.tf32.f32 "
    "{%0,%1,%2,%3}, {%4,%5,%6,%7}, {%8,%9}, {%0,%1,%2,%3};"
    : "+f"(c[0]), "+f"(c[1]), "+f"(c[2]), "+f"(c[3])
    : "r"(a[0]), "r"(a[1]), "r"(a[2]), "r"(a[3]), "r"(b[0]), "r"(b[1]));
}
__device__ __forceinline__ void cpa16(void* s, const void* g) {
  uint32_t sa = (uint32_t)__cvta_generic_to_shared(s);
  asm volatile("cp.async.cg.shared.global [%0], [%1], 16;" :: "r"(sa), "l"(g));
}
#define CPA_COMMIT asm volatile("cp.async.commit_group;" ::: "memory")
#define CPA_WAIT1  asm volatile("cp.async.wait_group 1;" ::: "memory")
#define CPA_WAIT0  asm volatile("cp.async.wait_group 0;" ::: "memory")
// MUFU-free exp: 2^(x*log2e), deg-6 poly + exponent bit inject.
__device__ __forceinline__ float fexp(float x) {
  float t = x * 1.4426950408889634f;
  float j = rintf(t);
  float f = t - j;
  float p = 1.53958971e-4f;
  p = fmaf(p, f, 1.33336498e-3f);
  p = fmaf(p, f, 9.61817851e-3f);
  p = fmaf(p, f, 5.55041087e-2f);
  p = fmaf(p, f, 2.40226507e-1f);
  p = fmaf(p, f, 6.93147181e-1f);
  p = fmaf(p, f, 1.0f);
  j = fmaxf(j, -126.f);
  return p * __int_as_float(((int)j + 127) << 23);
}

// ---------------- landmark conv via tf32 HMMA + LayerNorm + GELU + ql2 ----------------
__global__ __launch_bounds__(256) void k_land(const float* __restrict__ Q,
        const float* __restrict__ W, const float* __restrict__ gamma,
        const float* __restrict__ beta) {
  __shared__ __align__(16) char smraw[34304];
  float (*sA)[36] = (float(*)[36])smraw;
  float (*sB)[68] = (float(*)[68])(smraw + 18432);
  float (*Cs)[67] = (float(*)[67])smraw;
  int tid = threadIdx.x, w = tid >> 5, lane = tid & 31;
  int gid = lane >> 2, tig = lane & 3;
  int wm = w & 3, wn = w >> 2;
  int bh = blockIdx.z, m0 = blockIdx.y * 128;
  const float* Qb = Q + (size_t)bh * SN * 64;
  float acc[2][4][4] = {};
  int r = tid >> 1, kh = (tid & 1) * 16;
  int m = m0 + r;
  int py = m / 14, px = m % 14;
  for (int kc = 0; kc < 32; kc++) {
    int k0 = kc * 32;
    {
      int k = k0 + kh;
      int pix = k >> 6, ci = k & 63;
      int ry = pix >> 2, rx = pix & 3;
      float4 v[4] = {};
      if (m < SM) {
        int n = (py * 4 + ry) * SHW + px * 4 + rx;
        const float4* src = (const float4*)&Qb[(size_t)n * 64 + ci];
        #pragma unroll
        for (int e = 0; e < 4; e++) {
          float4 t = src[e];
          t.x *= QS; t.y *= QS; t.z *= QS; t.w *= QS;
          v[e] = t;
        }
      }
      #pragma unroll
      for (int e = 0; e < 4; e++) *(float4*)&sA[r][kh + e * 4] = v[e];
    }
    #pragma unroll
    for (int e = 0; e < 2; e++) {
      int t2 = tid * 2 + e;
      int tok = t2 >> 4, sg = t2 & 15;
      *(float4*)&sB[tok][sg * 4] = *(const float4*)&W[(size_t)(k0 + tok) * 64 + sg * 4];
    }
    __syncthreads();
    #pragma unroll
    for (int ks = 0; ks < 4; ks++) {
      int kb = ks * 8;
      uint32_t af[2][4], bf[4][2];
      #pragma unroll
      for (int mt = 0; mt < 2; mt++) {
        int row = wm * 32 + mt * 16 + gid;
        af[mt][0] = cvt_tf32(sA[row][kb + tig]);
        af[mt][1] = cvt_tf32(sA[row + 8][kb + tig]);
        af[mt][2] = cvt_tf32(sA[row][kb + tig + 4]);
        af[mt][3] = cvt_tf32(sA[row + 8][kb + tig + 4]);
      }
      #pragma unroll
      for (int nt = 0; nt < 4; nt++) {
        int nc = wn * 32 + nt * 8 + gid;
        bf[nt][0] = cvt_tf32(sB[kb + tig][nc]);
        bf[nt][1] = cvt_tf32(sB[kb + tig + 4][nc]);
      }
      #pragma unroll
      for (int mt = 0; mt < 2; mt++)
        #pragma unroll
        for (int nt = 0; nt < 4; nt++)
          mma_tf32(acc[mt][nt], af[mt], bf[nt]);
    }
    __syncthreads();
  }
  #pragma unroll
  for (int mt = 0; mt < 2; mt++)
    #pragma unroll
    for (int half = 0; half < 2; half++) {
      int rl = wm * 32 + mt * 16 + gid + half * 8;
      #pragma unroll
      for (int nt = 0; nt < 4; nt++) {
        int c = wn * 32 + nt * 8 + tig * 2;
        Cs[rl][c]     = acc[mt][nt][half * 2];
        Cs[rl][c + 1] = acc[mt][nt][half * 2 + 1];
      }
    }
  __syncthreads();
  if (tid < 128) {
    int p = m0 + tid;
    if (p < SM) {
      float mu = 0.f;
      #pragma unroll 8
      for (int j = 0; j < 64; j++) mu += Cs[tid][j];
      mu *= (1.f / 64.f);
      float s2 = 0.f;
      #pragma unroll 8
      for (int j = 0; j < 64; j++) { float d = Cs[tid][j] - mu; s2 += d * d; }
      float rr = rsqrtf(s2 * (1.f / 64.f) + 1e-5f);
      float q2 = 0.f;
      float* o = g_Ql + ((size_t)bh * SM + p) * 64;
      for (int j = 0; j < 64; j++) {
        float g = (Cs[tid][j] - mu) * rr * gamma[j] + beta[j];
        g = 0.5f * g * (1.f + erff(g * 0.7071067811865476f));
        q2 += g * g;
        o[j] = g;
      }
      g_ql2[bh * SM + p] = q2;
    }
  }
}

// ---------------- |scaled q_n|^2 ----------------
__global__ __launch_bounds__(256) void k_qn2(const float* __restrict__ Q) {
  int bh = blockIdx.y;
  int warp = threadIdx.x >> 5, lane = threadIdx.x & 31;
  int n = blockIdx.x * 8 + warp;
  const float* q = Q + ((size_t)bh * SN + n) * 64;
  float v0 = q[lane], v1 = q[lane + 32];
  float s = v0 * v0 + v1 * v1;
  #pragma unroll
  for (int o = 16; o; o >>= 1) s += __shfl_xor_sync(0xffffffffu, s, o);
  if (lane == 0) g_qn2[bh * SN + n] = s * (QS * QS);
}

// ---------------- unified gauss GEMM (tf32 HMMA + poly-exp) ----------------
__global__ __launch_bounds__(256) void k_gs(const float* __restrict__ A,
        const float* __restrict__ a2v, int Ma, float ascale, int pmode) {
  __shared__ __align__(16) float sA[128][36];
  __shared__ __align__(16) float sB[128][36];
  int tid = threadIdx.x, w = tid >> 5, lane = tid & 31;
  int gid = lane >> 2, tig = lane & 3;
  int wm = w & 3, wn = w >> 2;
  int bh = blockIdx.z, m0 = blockIdx.y * 128, n0 = blockIdx.x * 128;
  const float* Ab = A + (size_t)bh * Ma * 64;
  const float* Qlb = g_Ql + (size_t)bh * SM * 64;
  const float* a2b = a2v + (size_t)bh * Ma;
  const float* ql2b = g_ql2 + (size_t)bh * SM;
  float acc[2][8][4] = {};
  int r = tid >> 1, hb = (tid & 1) * 4;
  for (int kc = 0; kc < 2; kc++) {
    int k0 = kc * 32;
    int gm = m0 + r, gn = n0 + r;
    #pragma unroll
    for (int e = 0; e < 4; e++) {
      int c = (hb + e) * 4;
      float4 va = make_float4(0.f, 0.f, 0.f, 0.f);
      if (gm < Ma) va = *(const float4*)&Ab[(size_t)gm * 64 + k0 + c];
      va.x *= ascale; va.y *= ascale; va.z *= ascale; va.w *= ascale;
      *(float4*)&sA[r][c] = va;
      float4 vb = make_float4(0.f, 0.f, 0.f, 0.f);
      if (gn < SM) vb = *(const float4*)&Qlb[(size_t)gn * 64 + k0 + c];
      *(float4*)&sB[r][c] = vb;
    }
    __syncthreads();
    #pragma unroll
    for (int ks = 0; ks < 4; ks++) {
      int kb = ks * 8;
      uint32_t af[2][4], bf[8][2];
      #pragma unroll
      for (int mt = 0; mt < 2; mt++) {
        int row = wm * 32 + mt * 16 + gid;
        af[mt][0] = cvt_tf32(sA[row][kb + tig]);
        af[mt][1] = cvt_tf32(sA[row + 8][kb + tig]);
        af[mt][2] = cvt_tf32(sA[row][kb + tig + 4]);
        af[mt][3] = cvt_tf32(sA[row + 8][kb + tig + 4]);
      }
      #pragma unroll
      for (int nt = 0; nt < 8; nt++) {
        int brow = wn * 64 + nt * 8 + gid;
        bf[nt][0] = cvt_tf32(sB[brow][kb + tig]);
        bf[nt][1] = cvt_tf32(sB[brow][kb + tig + 4]);
      }
      #pragma unroll
      for (int mt = 0; mt < 2; mt++)
        #pragma unroll
        for (int nt = 0; nt < 8; nt++)
          mma_tf32(acc[mt][nt], af[mt], bf[nt]);
    }
    __syncthreads();
  }
  if (pmode) {
    float* P32 = g_P + (size_t)bh * SM * SM;
    __nv_bfloat16* Pbb = g_Pb + (size_t)bh * NSE;
    #pragma unroll
    for (int mt = 0; mt < 2; mt++) {
      #pragma unroll
      for (int half = 0; half < 2; half++) {
        int mm = m0 + wm * 32 + mt * 16 + gid + half * 8;
        float qm = (mm < SM) ? a2b[mm] : 0.f;
        #pragma unroll
        for (int nt = 0; nt < 8; nt++) {
          int n = n0 + wn * 64 + nt * 8 + tig * 2;
          float v0 = 0.f, v1 = 0.f;
          if (mm < SM) {
            if (n < SM)     v0 = fexp(acc[mt][nt][half * 2]     - 0.5f * (qm + ql2b[n]));
            if (n + 1 < SM) v1 = fexp(acc[mt][nt][half * 2 + 1] - 0.5f * (qm + ql2b[n + 1]));
          }
          *(uint32_t*)(Pbb + (size_t)mm * NSP + n) =
              pack2(__float2bfloat16(v0), __float2bfloat16(v1));
          if (mm < SM) {
            if (n < SM)     P32[(size_t)mm * SM + n] = v0;
            if (n + 1 < SM) P32[(size_t)mm * SM + n + 1] = v1;
          }
        }
      }
    }
  } else {
    __nv_bfloat16* k1b = g_k1 + (size_t)bh * SN * SMP;
    #pragma unroll
    for (int mt = 0; mt < 2; mt++) {
      #pragma unroll
      for (int half = 0; half < 2; half++) {
        int mm = m0 + wm * 32 + mt * 16 + gid + half * 8;
        if (mm >= SN) continue;
        float qm = a2b[mm];
        #pragma unroll
        for (int nt = 0; nt < 8; nt++) {
          int n = n0 + wn * 64 + nt * 8 + tig * 2;
          if (n + 1 >= SMP) continue;
          float v0 = 0.f, v1 = 0.f;
          if (n < SM)     v0 = fexp(acc[mt][nt][half * 2]     - 0.5f * (qm + ql2b[n]));
          if (n + 1 < SM) v1 = fexp(acc[mt][nt][half * 2 + 1] - 0.5f * (qm + ql2b[n + 1]));
          *(uint32_t*)(k1b + (size_t)mm * SMP + n) =
              pack2(__float2bfloat16(v0), __float2bfloat16(v1));
        }
      }
    }
  }
}

// ---------------- NS scale: g_nsc = 1/(n1*ninf) (P symmetric); also zero y0 ----------
__global__ __launch_bounds__(256) void k_scale() {
  int bh = blockIdx.x;
  const float* P = g_P + (size_t)bh * SM * SM;
  __shared__ float red[256];
  int tid = threadIdx.x;
  float rs = 0.f;
  if (tid < SM) {
    for (int j = 0; j < SM; j++) rs += fabsf(P[tid * SM + j]);
  }
  red[tid] = rs; __syncthreads();
  for (int s = 128; s > 0; s >>= 1) { if (tid < s) red[tid] = fmaxf(red[tid], red[tid + s]); __syncthreads(); }
  if (tid == 0) g_nsc[bh] = 1.f / (red[0] * red[0]);
  float4* yb = (float4*)(g_y0 + (size_t)bh * 256 * 64);
  for (int i = tid; i < 256 * 64 / 4; i += 256) yb[i] = make_float4(0.f, 0.f, 0.f, 0.f);
}

// =====================================================================================
// k_ns: merged Newton-Schulz step, uniform 4.2MF slots, 3 CTAs/SM.
//   Squaring slots (slot < nsq=6): 64x128 half-tile of D = Esq @ Esq.
//     quadrant q = slot>>1 in {0:(0,0), 1:(0,128)+mirror, 2:(128,128)}; half = slot&1.
//     initmode: Eout = I - s*D masked to [SM,SM]; else Eout = D.
//   Chain slots (slot >= nsq, 2 slots of 128 rows): yout = yin + Ech @ yin.
// =====================================================================================
__global__ __launch_bounds__(256, 3) void k_ns(
    const __nv_bfloat16* __restrict__ Esq, __nv_bfloat16* __restrict__ Eout,
    const __nv_bfloat16* __restrict__ Ech,
    const float* __restrict__ yin, float* __restrict__ yout,
    int nsq, int initmode) {
  __shared__ __align__(16) char smraw[30720];
  typedef __nv_bfloat16 (*TileP)[40];
  int tid = threadIdx.x, w = tid >> 5, lane = tid & 31;
  int gid = lane >> 2, tig = lane & 3;
  int bh = blockIdx.z, slot = blockIdx.x;
  size_t base = (size_t)bh * NSE;

  if (slot < nsq) {
    // ---------------- squaring half-tile: 64 rows x 128 cols, warps 2x4 --------------
    TileP sA0 = (TileP)(smraw);                       // 64 x 40
    TileP sA1 = (TileP)(smraw + 5120);
    TileP sB0 = (TileP)(smraw + 10240);               // 128 x 40
    TileP sB1 = (TileP)(smraw + 20480);
    int q = slot >> 1, half = slot & 1;
    int m0 = ((q == 2) ? 128 : 0) + half * 64;
    int n0 = (q >= 1) ? 128 : 0;
    int wm = w & 1, wn = w >> 1;                      // warp grid 2x4, tile 32x32
    const uint4* gE = (const uint4*)(Esq + base);
    float acc[2][4][4] = {};
    int r0 = tid >> 2, seg = tid & 3;                 // 64 A-rows: 1 cpa; 128 B-rows: 2
    cpa16(&sA0[r0][seg * 8],      gE + ((m0 + r0) * 32 + seg));
    cpa16(&sB0[r0][seg * 8],      gE + ((n0 + r0) * 32 + seg));
    cpa16(&sB0[r0 + 64][seg * 8], gE + ((n0 + r0 + 64) * 32 + seg));
    CPA_COMMIT;
    for (int kc = 0; kc < 8; kc++) {
      TileP cA = (kc & 1) ? sA1 : sA0;
      TileP cB = (kc & 1) ? sB1 : sB0;
      if (kc < 7) {
        TileP nA = (kc & 1) ? sA0 : sA1;
        TileP nB = (kc & 1) ? sB0 : sB1;
        int kn = (kc + 1) * 4;
        cpa16(&nA[r0][seg * 8],      gE + ((m0 + r0) * 32 + kn + seg));
        cpa16(&nB[r0][seg * 8],      gE + ((n0 + r0) * 32 + kn + seg));
        cpa16(&nB[r0 + 64][seg * 8], gE + ((n0 + r0 + 64) * 32 + kn + seg));
        CPA_COMMIT;
        CPA_WAIT1;
      } else {
        CPA_WAIT0;
      }
      __syncthreads();
      #pragma unroll
      for (int ks = 0; ks < 2; ks++) {
        int kb = ks * 16;
        uint32_t af[2][4], bf[4][2];
        #pragma unroll
        for (int mt = 0; mt < 2; mt++) {
          int row = wm * 32 + mt * 16 + gid;
          af[mt][0] = *(const uint32_t*)&cA[row][kb + tig * 2];
          af[mt][1] = *(const uint32_t*)&cA[row + 8][kb + tig * 2];
          af[mt][2] = *(const uint32_t*)&cA[row][kb + 8 + tig * 2];
          af[mt][3] = *(const uint32_t*)&cA[row + 8][kb + 8 + tig * 2];
        }
        #pragma unroll
        for (int nt = 0; nt < 4; nt++) {
          int brow = wn * 32 + nt * 8 + gid;
          bf[nt][0] = *(const uint32_t*)&cB[brow][kb + tig * 2];
          bf[nt][1] = *(const uint32_t*)&cB[brow][kb + 8 + tig * 2];
        }
        #pragma unroll
        for (int mt = 0; mt < 2; mt++)
          #pragma unroll
          for (int nt = 0; nt < 4; nt++)
            mma16816(acc[mt][nt], af[mt], bf[nt]);
      }
      __syncthreads();
    }
    float s = g_nsc[bh];
    __nv_bfloat16 (*tr)[129] = (__nv_bfloat16(*)[129])smraw;   // 64 x 129 mirror stage
    #pragma unroll
    for (int mt = 0; mt < 2; mt++) {
      #pragma unroll
      for (int nt = 0; nt < 4; nt++) {
        int row = m0 + wm * 32 + mt * 16 + gid;
        int col = n0 + wn * 32 + nt * 8 + tig * 2;
        #pragma unroll
        for (int hf = 0; hf < 2; hf++) {
          int r = row + hf * 8;
          float d0 = acc[mt][nt][hf * 2], d1 = acc[mt][nt][hf * 2 + 1];
          if (initmode) {
            d0 = (r < SM && col < SM) ? ((r == col ? 1.f : 0.f) - s * d0) : 0.f;
            d1 = (r < SM && col + 1 < SM) ? ((r == col + 1 ? 1.f : 0.f) - s * d1) : 0.f;
          }
          __nv_bfloat16 h0 = __float2bfloat16(d0), h1 = __float2bfloat16(d1);
          *(uint32_t*)(Eout + base + (size_t)r * NSP + col) = pack2(h0, h1);
          if (q == 1) {
            int rl = r - m0, cl = col - 128;
            tr[rl][cl] = h0;
            tr[rl][cl + 1] = h1;
          }
        }
      }
    }
    if (q == 1) {
      __syncthreads();
      // transposed coalesced store: Eout[128+cl][m0+rl] = tr[rl][cl]
      if (lane < 16) {
        #pragma unroll
        for (int i = 0; i < 16; i++) {
          int r2 = w * 16 + i;            // cl index (0..127) -> global row 128+r2
          int j = lane * 4;               // rl index (0..63)
          uint2 pk;
          pk.x = pack2(tr[j][r2], tr[j + 1][r2]);
          pk.y = pack2(tr[j + 2][r2], tr[j + 3][r2]);
          *(uint2*)(Eout + base + (size_t)(128 + r2) * NSP + m0 + j) = pk;
        }
      }
    }
  } else {
    // ---------------- chain role: yout = yin + Ech @ yin (128 rows per slot) ---------
    TileP sAc = (TileP)(smraw);                              // [128][40]
    __nv_bfloat16 (*sBy)[40] = (__nv_bfloat16(*)[40])(smraw + 10240);  // [64][40]
    int cslot = slot - nsq;
    int m0c = cslot * 128;
    int wm = w & 3, wn = w >> 2;
    const uint4* gAc = (const uint4*)(Ech + base);
    const float* yb_in = yin + (size_t)bh * 256 * 64;
    float* yb_out = yout + (size_t)bh * 256 * 64;
    float acc[2][4][4] = {};
    int r0 = tid >> 2, seg = tid & 3;
    int kk = tid & 31, nb = (tid >> 5) * 8;
    for (int kc = 0; kc < 8; kc++) {
      *(uint4*)&sAc[r0][seg * 8]      = gAc[(m0c + r0) * 32 + kc * 4 + seg];
      *(uint4*)&sAc[r0 + 64][seg * 8] = gAc[(m0c + r0 + 64) * 32 + kc * 4 + seg];
      #pragma unroll
      for (int i = 0; i < 8; i++)
        sBy[nb + i][kk] = __float2bfloat16(yb_in[(size_t)(kc * 32 + kk) * 64 + nb + i]);
      __syncthreads();
      #pragma unroll
      for (int ks = 0; ks < 2; ks++) {
        int kb = ks * 16;
        uint32_t af[2][4], bf[4][2];
        #pragma unroll
        for (int mt = 0; mt < 2; mt++) {
          int row = wm * 32 + mt * 16 + gid;
          af[mt][0] = *(const uint32_t*)&sAc[row][kb + tig * 2];
          af[mt][1] = *(const uint32_t*)&sAc[row + 8][kb + tig * 2];
          af[mt][2] = *(const uint32_t*)&sAc[row][kb + 8 + tig * 2];
          af[mt][3] = *(const uint32_t*)&sAc[row + 8][kb + 8 + tig * 2];
        }
        #pragma unroll
        for (int nt = 0; nt < 4; nt++) {
          int brow = wn * 32 + nt * 8 + gid;
          bf[nt][0] = *(const uint32_t*)&sBy[brow][kb + tig * 2];
          bf[nt][1] = *(const uint32_t*)&sBy[brow][kb + 8 + tig * 2];
        }
        #pragma unroll
        for (int mt = 0; mt < 2; mt++)
          #pragma unroll
          for (int nt = 0; nt < 4; nt++)
            mma16816(acc[mt][nt], af[mt], bf[nt]);
      }
      __syncthreads();
    }
    #pragma unroll
    for (int mt = 0; mt < 2; mt++)
      #pragma unroll
      for (int hf = 0; hf < 2; hf++) {
        int mr = m0c + wm * 32 + mt * 16 + gid + hf * 8;
        #pragma unroll
        for (int nt = 0; nt < 4; nt++) {
          int col = wn * 32 + nt * 8 + tig * 2;
          yb_out[(size_t)mr * 64 + col] =
              yb_in[(size_t)mr * 64 + col] + acc[mt][nt][hf * 2];
          yb_out[(size_t)mr * 64 + col + 1] =
              yb_in[(size_t)mr * 64 + col + 1] + acc[mt][nt][hf * 2 + 1];
        }
      }
  }
}

// ---------------- k_fin: y20 = (I+E19) y19 ; Y = s * Pb @ y20. One CTA per bh. -------
__global__ __launch_bounds__(256) void k_fin(
    const __nv_bfloat16* __restrict__ E19, const __nv_bfloat16* __restrict__ Pb,
    const float* __restrict__ yin, float* __restrict__ ymid, float* __restrict__ yout) {
  __shared__ __align__(16) char smraw[15360];
  typedef __nv_bfloat16 (*TileP)[40];
  TileP sAc = (TileP)(smraw);
  __nv_bfloat16 (*sBy)[40] = (__nv_bfloat16(*)[40])(smraw + 10240);
  int tid = threadIdx.x, w = tid >> 5, lane = tid & 31;
  int gid = lane >> 2, tig = lane & 3;
  int wm = w & 3, wn = w >> 2;
  int bh = blockIdx.x;
  size_t base = (size_t)bh * NSE;
  float s = g_nsc[bh];
  int r0 = tid >> 2, seg = tid & 3;
  int kk = tid & 31, nb = (tid >> 5) * 8;
  #pragma unroll
  for (int st = 0; st < 2; st++) {
    const uint4* gAc = (const uint4*)((st ? Pb : E19) + base);
    const float* yi = (st ? ymid : yin) + (size_t)bh * 256 * 64;
    float* yo = (st ? yout : ymid) + (size_t)bh * 256 * 64;
    if (st) __syncthreads();
    #pragma unroll
    for (int pass = 0; pass < 2; pass++) {
      int m0c = pass * 128;
      float acc[2][4][4] = {};
      for (int kc = 0; kc < 8; kc++) {
        *(uint4*)&sAc[r0][seg * 8]      = gAc[(m0c + r0) * 32 + kc * 4 + seg];
        *(uint4*)&sAc[r0 + 64][seg * 8] = gAc[(m0c + r0 + 64) * 32 + kc * 4 + seg];
        #pragma unroll
        for (int i = 0; i < 8; i++)
          sBy[nb + i][kk] = __float2bfloat16(yi[(size_t)(kc * 32 + kk) * 64 + nb + i]);
        __syncthreads();
        #pragma unroll
        for (int ks = 0; ks < 2; ks++) {
          int kb = ks * 16;
          uint32_t af[2][4], bf[4][2];
          #pragma unroll
          for (int mt = 0; mt < 2; mt++) {
            int row = wm * 32 + mt * 16 + gid;
            af[mt][0] = *(const uint32_t*)&sAc[row][kb + tig * 2];
            af[mt][1] = *(const uint32_t*)&sAc[row + 8][kb + tig * 2];
            af[mt][2] = *(const uint32_t*)&sAc[row][kb + 8 + tig * 2];
            af[mt][3] = *(const uint32_t*)&sAc[row + 8][kb + 8 + tig * 2];
          }
          #pragma unroll
          for (int nt = 0; nt < 4; nt++) {
            int brow = wn * 32 + nt * 8 + gid;
            bf[nt][0] = *(const uint32_t*)&sBy[brow][kb + tig * 2];
            bf[nt][1] = *(const uint32_t*)&sBy[brow][kb + 8 + tig * 2];
          }
          #pragma unroll
          for (int mt = 0; mt < 2; mt++)
            #pragma unroll
            for (int nt = 0; nt < 4; nt++)
              mma16816(acc[mt][nt], af[mt], bf[nt]);
        }
        __syncthreads();
      }
      #pragma unroll
      for (int mt = 0; mt < 2; mt++)
        #pragma unroll
        for (int hf = 0; hf < 2; hf++) {
          int mr = m0c + wm * 32 + mt * 16 + gid + hf * 8;
          #pragma unroll
          for (int nt = 0; nt < 4; nt++) {
            int col = wn * 32 + nt * 8 + tig * 2;
            float d0 = acc[mt][nt][hf * 2], d1 = acc[mt][nt][hf * 2 + 1];
            float o0, o1;
            if (st) { o0 = s * d0; o1 = s * d1; }
            else {
              o0 = yi[(size_t)mr * 64 + col] + d0;
              o1 = yi[(size_t)mr * 64 + col + 1] + d1;
            }
            yo[(size_t)mr * 64 + col] = o0;
            yo[(size_t)mr * 64 + col + 1] = o1;
          }
        }
    }
  }
}

// ---------------- y0 += slice of Z = k1^T @ V (bf16 HMMA, K split over grid.x) --------
__global__ __launch_bounds__(256) void k_Zt(const float* __restrict__ V,
                                            float* __restrict__ y0) {
  __shared__ __align__(16) __nv_bfloat16 sA[128][40];   // [landmark][token]
  __shared__ __align__(16) __nv_bfloat16 sB[64][40];    // [channel][token]
  int tid = threadIdx.x, w = tid >> 5, lane = tid & 31;
  int gid = lane >> 2, tig = lane & 3;
  int wm = w & 3, wn = w >> 2;
  int bh = blockIdx.z, m0 = blockIdx.y * 128, kslice = blockIdx.x;
  const __nv_bfloat16* k1b = g_k1 + (size_t)bh * SN * SMP;
  const float* Vb = V + (size_t)bh * SN * 64;
  float acc[2][4][4] = {};
  int tokA = tid & 31, segA = tid >> 5;
  int cB = tid & 63, gB = tid >> 6;
  for (int kc = kslice * 14; kc < kslice * 14 + 14; kc++) {
    int k0 = kc * 32;
    const __nv_bfloat16* k1r = k1b + (size_t)(k0 + tokA) * SMP;
    #pragma unroll
    for (int i = 0; i < 4; i++) {
      int l = segA * 16 + i * 4;
      int gl = m0 + l;
      __align__(8) __nv_bfloat16 v4[4];
      if (gl + 3 < SMP) *(uint2*)v4 = *(const uint2*)&k1r[gl];
      else { v4[0] = v4[1] = v4[2] = v4[3] = __float2bfloat16(0.f); }
      sA[l][tokA] = v4[0]; sA[l + 1][tokA] = v4[1];
      sA[l + 2][tokA] = v4[2]; sA[l + 3][tokA] = v4[3];
    }
    #pragma unroll
    for (int i = 0; i < 8; i++) {
      int t = gB * 8 + i;
      sB[cB][t] = __float2bfloat16(Vb[(size_t)(k0 + t) * 64 + cB]);
    }
    __syncthreads();
    #pragma unroll
    for (int ks = 0; ks < 2; ks++) {
      int kb = ks * 16;
      uint32_t af[2][4], bf[4][2];
      #pragma unroll
      for (int mt = 0; mt < 2; mt++) {
        int row = wm * 32 + mt * 16 + gid;
        af[mt][0] = *(const uint32_t*)&sA[row][kb + tig * 2];
        af[mt][1] = *(const uint32_t*)&sA[row + 8][kb + tig * 2];
        af[mt][2] = *(const uint32_t*)&sA[row][kb + 8 + tig * 2];
        af[mt][3] = *(const uint32_t*)&sA[row + 8][kb + 8 + tig * 2];
      }
      #pragma unroll
      for (int nt = 0; nt < 4; nt++) {
        int brow = wn * 32 + nt * 8 + gid;
        bf[nt][0] = *(const uint32_t*)&sB[brow][kb + tig * 2];
        bf[nt][1] = *(const uint32_t*)&sB[brow][kb + 8 + tig * 2];
      }
      #pragma unroll
      for (int mt = 0; mt < 2; mt++)
        #pragma unroll
        for (int nt = 0; nt < 4; nt++)
          mma16816(acc[mt][nt], af[mt], bf[nt]);
    }
    __syncthreads();
  }
  float* yb = y0 + (size_t)bh * 256 * 64;
  #pragma unroll
  for (int mt = 0; mt < 2; mt++)
    #pragma unroll
    for (int hf = 0; hf < 2; hf++) {
      int mr = m0 + wm * 32 + mt * 16 + gid + hf * 8;
      #pragma unroll
      for (int nt = 0; nt < 4; nt++) {
        int n = wn * 32 + nt * 8 + tig * 2;
        atomicAdd(&yb[(size_t)mr * 64 + n],     acc[mt][nt][hf * 2]);
        atomicAdd(&yb[(size_t)mr * 64 + n + 1], acc[mt][nt][hf * 2 + 1]);
      }
    }
}

// ---------------- depthwise 3x3 conv residual -> d_out ----------------
__global__ __launch_bounds__(256) void k_conv(const float* __restrict__ V,
        const float* __restrict__ cw, float* __restrict__ out) {
  int bh = blockIdx.y;
  int h = bh & 7;
  int e = blockIdx.x * 256 + threadIdx.x;
  int c = e & 63, n = e >> 6;
  int y = n / SHW, x = n % SHW;
  const float* Vb = V + (size_t)bh * SN * 64;
  float acc = 0.f;
  #pragma unroll
  for (int dy = -1; dy <= 1; dy++)
    #pragma unroll
    for (int dx = -1; dx <= 1; dx++) {
      int yy = y + dy, xx = x + dx;
      if ((unsigned)yy < SHW && (unsigned)xx < SHW)
        acc += cw[((dy + 1) * 3 + (dx + 1)) * 8 + h] * Vb[(yy * SHW + xx) * 64 + c];
    }
  out[(size_t)bh * SN * 64 + e] = acc;
}

// ---------------- out += k1 @ Y (bf16 HMMA, K=224 in 7 chunks) ----------------
__global__ __launch_bounds__(256) void k_Xt(const float* __restrict__ Yf,
                                            float* __restrict__ out) {
  __shared__ __align__(16) __nv_bfloat16 sA[128][40];
  __shared__ __align__(16) __nv_bfloat16 sB[64][40];
  int tid = threadIdx.x, w = tid >> 5, lane = tid & 31;
  int gid = lane >> 2, tig = lane & 3;
  int wm = w & 3, wn = w >> 2;
  int bh = blockIdx.z, m0 = blockIdx.y * 128;
  const __nv_bfloat16* k1b = g_k1 + (size_t)bh * SN * SMP;
  const float* Yb = Yf + (size_t)bh * 256 * 64;
  float acc[2][4][4] = {};
  int r0 = tid >> 2, seg = tid & 3;
  int cB = tid & 63, gB = tid >> 6;
  for (int kc = 0; kc < 7; kc++) {
    int k0 = kc * 32;
    #pragma unroll
    for (int rr = 0; rr < 2; rr++) {
      int gm = m0 + r0 + rr * 64;
      uint4 v = make_uint4(0, 0, 0, 0);
      if (gm < SN) v = *(const uint4*)&k1b[(size_t)gm * SMP + k0 + seg * 8];
      *(uint4*)&sA[r0 + rr * 64][seg * 8] = v;
    }
    #pragma unroll
    for (int i = 0; i < 8; i++) {
      int t = gB * 8 + i;
      sB[cB][t] = __float2bfloat16(Yb[(size_t)(k0 + t) * 64 + cB]);
    }
    __syncthreads();
    #pragma unroll
    for (int ks = 0; ks < 2; ks++) {
      int kb = ks * 16;
      uint32_t af[2][4], bf[4][2];
      #pragma unroll
      for (int mt = 0; mt < 2; mt++) {
        int row = wm * 32 + mt * 16 + gid;
        af[mt][0] = *(const uint32_t*)&sA[row][kb + tig * 2];
        af[mt][1] = *(const uint32_t*)&sA[row + 8][kb + tig * 2];
        af[mt][2] = *(const uint32_t*)&sA[row][kb + 8 + tig * 2];
        af[mt][3] = *(const uint32_t*)&sA[row + 8][kb + 8 + tig * 2];
      }
      #pragma unroll
      for (int nt = 0; nt < 4; nt++) {
        int brow = wn * 32 + nt * 8 + gid;
        bf[nt][0] = *(const uint32_t*)&sB[brow][kb + tig * 2];
        bf[nt][1] = *(const uint32_t*)&sB[brow][kb + 8 + tig * 2];
      }
      #pragma unroll
      for (int mt = 0; mt < 2; mt++)
        #pragma unroll
        for (int nt = 0; nt < 4; nt++)
          mma16816(acc[mt][nt], af[mt], bf[nt]);
    }
    __syncthreads();
  }
  float* ob = out + (size_t)bh * SN * 64;
  #pragma unroll
  for (int mt = 0; mt < 2; mt++)
    #pragma unroll
    for (int hf = 0; hf < 2; hf++) {
      int mr = m0 + wm * 32 + mt * 16 + gid + hf * 8;
      if (mr >= SN) continue;
      #pragma unroll
      for (int nt = 0; nt < 4; nt++) {
        int n = wn * 32 + nt * 8 + tig * 2;
        ob[(size_t)mr * 64 + n]     += acc[mt][nt][hf * 2];
        ob[(size_t)mr * 64 + n + 1] += acc[mt][nt][hf * 2 + 1];
      }
    }
}

// ---------------- host launch ----------------
extern "C" void kernel_launch(void* const* d_in, const int* in_sizes, int n_in,
                              void* d_out, int out_size) {
  const float* Q     = (const float*)d_in[0];
  const float* V     = (const float*)d_in[1];
  const float* wl    = (const float*)d_in[2];
  const float* gamma = (const float*)d_in[3];
  const float* beta  = (const float*)d_in[4];
  const float* cw    = (const float*)d_in[5];
  float* out = (float*)d_out;

  float *pQl, *pql2, *pqn2, *py0, *py1;
  cudaGetSymbolAddress((void**)&pQl,  g_Ql);
  cudaGetSymbolAddress((void**)&pql2, g_ql2);
  cudaGetSymbolAddress((void**)&pqn2, g_qn2);
  cudaGetSymbolAddress((void**)&py0,  g_y0);
  cudaGetSymbolAddress((void**)&py1,  g_y1);
  __nv_bfloat16 *pEa, *pEb, *pPb;
  cudaGetSymbolAddress((void**)&pPb, g_Pb);
  cudaGetSymbolAddress((void**)&pEa, g_Ea);
  cudaGetSymbolAddress((void**)&pEb, g_Eb);

  // landmarks, P, scale (+zero y0), NS init (6 half-tile slots)
  k_land<<<dim3(1, 2, SBH), 256>>>(Q, wl, gamma, beta);
  k_gs<<<dim3(2, 2, SBH), 256>>>(pQl, pql2, SM, 1.f, 1);
  k_scale<<<SBH, 256>>>();
  k_ns<<<dim3(6, 1, SBH), 256>>>(pPb, pEa, nullptr, nullptr, nullptr, 6, 1);
  // k1 path (independent of NS)
  k_qn2<<<dim3(SN / 8, SBH), 256>>>(Q);
  k_gs<<<dim3(2, 25, SBH), 256>>>(Q, pqn2, SN, QS, 0);
  k_Zt<<<dim3(7, 2, SBH), 256>>>(V, py0);
  // 19 merged steps: E^2 (6 uniform half-tile slots) + chain (2 slots)
  __nv_bfloat16 *ec = pEa, *en = pEb;
  float *yc = py0, *yn = py1;
  for (int k = 0; k < 19; k++) {
    k_ns<<<dim3(8, 1, SBH), 256>>>(ec, en, ec, yc, yn, 6, 0);
    __nv_bfloat16* te = ec; ec = en; en = te;
    float* ty = yc; yc = yn; yn = ty;
  }
  // y20 = (I+E19) y19 ; Y = s * Pb @ y20   (single fused launch)
  k_fin<<<SBH, 256>>>(ec, pPb, yc, yn, yc);
  // conv residual -> out, then out += k1 @ Y
  k_conv<<<dim3(784, SBH), 256>>>(V, cw, out);
  k_Xt<<<dim3(1, 25, SBH), 256>>>(yc, out);
}

// round 17
// speedup vs baseline: 1.0966x; 1.0966x over previous
#include <cuda_runtime.h>
#include <cuda_bf16.h>
#include <math.h>
#include <stdint.h>

#define SBH 128
#define SN  3136
#define SM  196
#define SMP 224                    /* k1 row stride (bf16), 32-aligned, zero-padded */
#define SHW 56
#define QS  0.35355339059327379f   /* 64^-0.25 */
#define NSP 256
#define NSE ((size_t)(NSP*NSP))

// ---------------- scratch (static device globals; no allocation) ----------------
__device__ float g_Ql [SBH*SM*64];
__device__ float g_ql2[SBH*SM];
__device__ float g_qn2[SBH*SN];
__device__ __align__(16) __nv_bfloat16 g_k1[(size_t)SBH*SN*SMP];   // 180 MB bf16
__device__ float g_P  [SBH*SM*SM];
__device__ float g_nsc[SBH];
__device__ __align__(16) __nv_bfloat16 g_Pb[SBH*NSE];   // bf16 P, padded 256x256
__device__ __align__(16) __nv_bfloat16 g_Ea[SBH*NSE];   // E ping
__device__ __align__(16) __nv_bfloat16 g_Eb[SBH*NSE];   // E pong
__device__ __align__(16) float g_y0[SBH*256*64];        // y ping (fp32)
__device__ __align__(16) float g_y1[SBH*256*64];        // y pong

// ================= helpers =================
__device__ __forceinline__ uint32_t pack2(__nv_bfloat16 a, __nv_bfloat16 b) {
  return (uint32_t)__bfloat16_as_ushort(a) | ((uint32_t)__bfloat16_as_ushort(b) << 16);
}
__device__ __forceinline__ void mma16816(float* c, const uint32_t* a, const uint32_t* b) {
  asm volatile(
    "mma.sync.aligned.m16n8k16.row.col.f32.bf16.bf16.f32 "
    "{%0,%1,%2,%3}, {%4,%5,%6,%7}, {%8,%9}, {%0,%1,%2,%3};"
    : "+f"(c[0]), "+f"(c[1]), "+f"(c[2]), "+f"(c[3])
    : "r"(a[0]), "r"(a[1]), "r"(a[2]), "r"(a[3]), "r"(b[0]), "r"(b[1]));
}
__device__ __forceinline__ uint32_t cvt_tf32(float x) {
  uint32_t r; asm("cvt.rna.tf32.f32 %0, %1;" : "=r"(r) : "f"(x)); return r;
}
__device__ __forceinline__ void mma_tf32(float* c, const uint32_t* a, const uint32_t* b) {
  asm volatile(
    "mma.sync.aligned.m16n8k8.row.col.f32.tf32.tf32.f32 "
    "{%0,%1,%2,%3}, {%4,%5,%6,%7}, {%8,%9}, {%0,%1,%2,%3};"
    : "+f"(c[0]), "+f"(c[1]), "+f"(c[2]), "+f"(c[3])
    : "r"(a[0]), "r"(a[1]), "r"(a[2]), "r"(a[3]), "r"(b[0]), "r"(b[1]));
}
__device__ __forceinline__ void cpa16(void* s, const void* g) {
  uint32_t sa = (uint32_t)__cvta_generic_to_shared(s);
  asm volatile("cp.async.cg.shared.global [%0], [%1], 16;" :: "r"(sa), "l"(g));
}
#define CPA_COMMIT asm volatile("cp.async.commit_group;" ::: "memory")
#define CPA_WAIT1  asm volatile("cp.async.wait_group 1;" ::: "memory")
#define CPA_WAIT0  asm volatile("cp.async.wait_group 0;" ::: "memory")
// MUFU-free exp: 2^(x*log2e), deg-6 poly + exponent bit inject.
__device__ __forceinline__ float fexp(float x) {
  float t = x * 1.4426950408889634f;
  float j = rintf(t);
  float f = t - j;
  float p = 1.53958971e-4f;
  p = fmaf(p, f, 1.33336498e-3f);
  p = fmaf(p, f, 9.61817851e-3f);
  p = fmaf(p, f, 5.55041087e-2f);
  p = fmaf(p, f, 2.40226507e-1f);
  p = fmaf(p, f, 6.93147181e-1f);
  p = fmaf(p, f, 1.0f);
  j = fmaxf(j, -126.f);
  return p * __int_as_float(((int)j + 127) << 23);
}

// ---------------- landmark conv via tf32 HMMA + LayerNorm + GELU + ql2 ----------------
__global__ __launch_bounds__(256) void k_land(const float* __restrict__ Q,
        const float* __restrict__ W, const float* __restrict__ gamma,
        const float* __restrict__ beta) {
  __shared__ __align__(16) char smraw[34304];
  float (*sA)[36] = (float(*)[36])smraw;
  float (*sB)[68] = (float(*)[68])(smraw + 18432);
  float (*Cs)[67] = (float(*)[67])smraw;
  int tid = threadIdx.x, w = tid >> 5, lane = tid & 31;
  int gid = lane >> 2, tig = lane & 3;
  int wm = w & 3, wn = w >> 2;
  int bh = blockIdx.z, m0 = blockIdx.y * 128;
  const float* Qb = Q + (size_t)bh * SN * 64;
  float acc[2][4][4] = {};
  int r = tid >> 1, kh = (tid & 1) * 16;
  int m = m0 + r;
  int py = m / 14, px = m % 14;
  for (int kc = 0; kc < 32; kc++) {
    int k0 = kc * 32;
    {
      int k = k0 + kh;
      int pix = k >> 6, ci = k & 63;
      int ry = pix >> 2, rx = pix & 3;
      float4 v[4] = {};
      if (m < SM) {
        int n = (py * 4 + ry) * SHW + px * 4 + rx;
        const float4* src = (const float4*)&Qb[(size_t)n * 64 + ci];
        #pragma unroll
        for (int e = 0; e < 4; e++) {
          float4 t = src[e];
          t.x *= QS; t.y *= QS; t.z *= QS; t.w *= QS;
          v[e] = t;
        }
      }
      #pragma unroll
      for (int e = 0; e < 4; e++) *(float4*)&sA[r][kh + e * 4] = v[e];
    }
    #pragma unroll
    for (int e = 0; e < 2; e++) {
      int t2 = tid * 2 + e;
      int tok = t2 >> 4, sg = t2 & 15;
      *(float4*)&sB[tok][sg * 4] = *(const float4*)&W[(size_t)(k0 + tok) * 64 + sg * 4];
    }
    __syncthreads();
    #pragma unroll
    for (int ks = 0; ks < 4; ks++) {
      int kb = ks * 8;
      uint32_t af[2][4], bf[4][2];
      #pragma unroll
      for (int mt = 0; mt < 2; mt++) {
        int row = wm * 32 + mt * 16 + gid;
        af[mt][0] = cvt_tf32(sA[row][kb + tig]);
        af[mt][1] = cvt_tf32(sA[row + 8][kb + tig]);
        af[mt][2] = cvt_tf32(sA[row][kb + tig + 4]);
        af[mt][3] = cvt_tf32(sA[row + 8][kb + tig + 4]);
      }
      #pragma unroll
      for (int nt = 0; nt < 4; nt++) {
        int nc = wn * 32 + nt * 8 + gid;
        bf[nt][0] = cvt_tf32(sB[kb + tig][nc]);
        bf[nt][1] = cvt_tf32(sB[kb + tig + 4][nc]);
      }
      #pragma unroll
      for (int mt = 0; mt < 2; mt++)
        #pragma unroll
        for (int nt = 0; nt < 4; nt++)
          mma_tf32(acc[mt][nt], af[mt], bf[nt]);
    }
    __syncthreads();
  }
  #pragma unroll
  for (int mt = 0; mt < 2; mt++)
    #pragma unroll
    for (int half = 0; half < 2; half++) {
      int rl = wm * 32 + mt * 16 + gid + half * 8;
      #pragma unroll
      for (int nt = 0; nt < 4; nt++) {
        int c = wn * 32 + nt * 8 + tig * 2;
        Cs[rl][c]     = acc[mt][nt][half * 2];
        Cs[rl][c + 1] = acc[mt][nt][half * 2 + 1];
      }
    }
  __syncthreads();
  if (tid < 128) {
    int p = m0 + tid;
    if (p < SM) {
      float mu = 0.f;
      #pragma unroll 8
      for (int j = 0; j < 64; j++) mu += Cs[tid][j];
      mu *= (1.f / 64.f);
      float s2 = 0.f;
      #pragma unroll 8
      for (int j = 0; j < 64; j++) { float d = Cs[tid][j] - mu; s2 += d * d; }
      float rr = rsqrtf(s2 * (1.f / 64.f) + 1e-5f);
      float q2 = 0.f;
      float* o = g_Ql + ((size_t)bh * SM + p) * 64;
      for (int j = 0; j < 64; j++) {
        float g = (Cs[tid][j] - mu) * rr * gamma[j] + beta[j];
        g = 0.5f * g * (1.f + erff(g * 0.7071067811865476f));
        q2 += g * g;
        o[j] = g;
      }
      g_ql2[bh * SM + p] = q2;
    }
  }
}

// ---------------- |scaled q_n|^2 ----------------
__global__ __launch_bounds__(256) void k_qn2(const float* __restrict__ Q) {
  int bh = blockIdx.y;
  int warp = threadIdx.x >> 5, lane = threadIdx.x & 31;
  int n = blockIdx.x * 8 + warp;
  const float* q = Q + ((size_t)bh * SN + n) * 64;
  float v0 = q[lane], v1 = q[lane + 32];
  float s = v0 * v0 + v1 * v1;
  #pragma unroll
  for (int o = 16; o; o >>= 1) s += __shfl_xor_sync(0xffffffffu, s, o);
  if (lane == 0) g_qn2[bh * SN + n] = s * (QS * QS);
}

// ---------------- unified gauss GEMM (tf32 HMMA + poly-exp) ----------------
__global__ __launch_bounds__(256) void k_gs(const float* __restrict__ A,
        const float* __restrict__ a2v, int Ma, float ascale, int pmode) {
  __shared__ __align__(16) float sA[128][36];
  __shared__ __align__(16) float sB[128][36];
  int tid = threadIdx.x, w = tid >> 5, lane = tid & 31;
  int gid = lane >> 2, tig = lane & 3;
  int wm = w & 3, wn = w >> 2;
  int bh = blockIdx.z, m0 = blockIdx.y * 128, n0 = blockIdx.x * 128;
  const float* Ab = A + (size_t)bh * Ma * 64;
  const float* Qlb = g_Ql + (size_t)bh * SM * 64;
  const float* a2b = a2v + (size_t)bh * Ma;
  const float* ql2b = g_ql2 + (size_t)bh * SM;
  float acc[2][8][4] = {};
  int r = tid >> 1, hb = (tid & 1) * 4;
  for (int kc = 0; kc < 2; kc++) {
    int k0 = kc * 32;
    int gm = m0 + r, gn = n0 + r;
    #pragma unroll
    for (int e = 0; e < 4; e++) {
      int c = (hb + e) * 4;
      float4 va = make_float4(0.f, 0.f, 0.f, 0.f);
      if (gm < Ma) va = *(const float4*)&Ab[(size_t)gm * 64 + k0 + c];
      va.x *= ascale; va.y *= ascale; va.z *= ascale; va.w *= ascale;
      *(float4*)&sA[r][c] = va;
      float4 vb = make_float4(0.f, 0.f, 0.f, 0.f);
      if (gn < SM) vb = *(const float4*)&Qlb[(size_t)gn * 64 + k0 + c];
      *(float4*)&sB[r][c] = vb;
    }
    __syncthreads();
    #pragma unroll
    for (int ks = 0; ks < 4; ks++) {
      int kb = ks * 8;
      uint32_t af[2][4], bf[8][2];
      #pragma unroll
      for (int mt = 0; mt < 2; mt++) {
        int row = wm * 32 + mt * 16 + gid;
        af[mt][0] = cvt_tf32(sA[row][kb + tig]);
        af[mt][1] = cvt_tf32(sA[row + 8][kb + tig]);
        af[mt][2] = cvt_tf32(sA[row][kb + tig + 4]);
        af[mt][3] = cvt_tf32(sA[row + 8][kb + tig + 4]);
      }
      #pragma unroll
      for (int nt = 0; nt < 8; nt++) {
        int brow = wn * 64 + nt * 8 + gid;
        bf[nt][0] = cvt_tf32(sB[brow][kb + tig]);
        bf[nt][1] = cvt_tf32(sB[brow][kb + tig + 4]);
      }
      #pragma unroll
      for (int mt = 0; mt < 2; mt++)
        #pragma unroll
        for (int nt = 0; nt < 8; nt++)
          mma_tf32(acc[mt][nt], af[mt], bf[nt]);
    }
    __syncthreads();
  }
  if (pmode) {
    float* P32 = g_P + (size_t)bh * SM * SM;
    __nv_bfloat16* Pbb = g_Pb + (size_t)bh * NSE;
    #pragma unroll
    for (int mt = 0; mt < 2; mt++) {
      #pragma unroll
      for (int half = 0; half < 2; half++) {
        int mm = m0 + wm * 32 + mt * 16 + gid + half * 8;
        float qm = (mm < SM) ? a2b[mm] : 0.f;
        #pragma unroll
        for (int nt = 0; nt < 8; nt++) {
          int n = n0 + wn * 64 + nt * 8 + tig * 2;
          float v0 = 0.f, v1 = 0.f;
          if (mm < SM) {
            if (n < SM)     v0 = fexp(acc[mt][nt][half * 2]     - 0.5f * (qm + ql2b[n]));
            if (n + 1 < SM) v1 = fexp(acc[mt][nt][half * 2 + 1] - 0.5f * (qm + ql2b[n + 1]));
          }
          *(uint32_t*)(Pbb + (size_t)mm * NSP + n) =
              pack2(__float2bfloat16(v0), __float2bfloat16(v1));
          if (mm < SM) {
            if (n < SM)     P32[(size_t)mm * SM + n] = v0;
            if (n + 1 < SM) P32[(size_t)mm * SM + n + 1] = v1;
          }
        }
      }
    }
  } else {
    __nv_bfloat16* k1b = g_k1 + (size_t)bh * SN * SMP;
    #pragma unroll
    for (int mt = 0; mt < 2; mt++) {
      #pragma unroll
      for (int half = 0; half < 2; half++) {
        int mm = m0 + wm * 32 + mt * 16 + gid + half * 8;
        if (mm >= SN) continue;
        float qm = a2b[mm];
        #pragma unroll
        for (int nt = 0; nt < 8; nt++) {
          int n = n0 + wn * 64 + nt * 8 + tig * 2;
          if (n + 1 >= SMP) continue;
          float v0 = 0.f, v1 = 0.f;
          if (n < SM)     v0 = fexp(acc[mt][nt][half * 2]     - 0.5f * (qm + ql2b[n]));
          if (n + 1 < SM) v1 = fexp(acc[mt][nt][half * 2 + 1] - 0.5f * (qm + ql2b[n + 1]));
          *(uint32_t*)(k1b + (size_t)mm * SMP + n) =
              pack2(__float2bfloat16(v0), __float2bfloat16(v1));
        }
      }
    }
  }
}

// ---------------- NS scale: g_nsc = 1/(n1*ninf) (P symmetric); also zero y0 ----------
__global__ __launch_bounds__(256) void k_scale() {
  int bh = blockIdx.x;
  const float* P = g_P + (size_t)bh * SM * SM;
  __shared__ float red[256];
  int tid = threadIdx.x;
  float rs = 0.f;
  if (tid < SM) {
    for (int j = 0; j < SM; j++) rs += fabsf(P[tid * SM + j]);
  }
  red[tid] = rs; __syncthreads();
  for (int s = 128; s > 0; s >>= 1) { if (tid < s) red[tid] = fmaxf(red[tid], red[tid + s]); __syncthreads(); }
  if (tid == 0) g_nsc[bh] = 1.f / (red[0] * red[0]);
  float4* yb = (float4*)(g_y0 + (size_t)bh * 256 * 64);
  for (int i = tid; i < 256 * 64 / 4; i += 256) yb[i] = make_float4(0.f, 0.f, 0.f, 0.f);
}

// =====================================================================================
// k_ns: merged Newton-Schulz step (round-13 champion structure).
//   Squaring slots (slot < nsq=3): D = Esq @ Esq; slot0=(0,0), slot1=(0,1)+mirror
//     via smem transpose, slot2=(1,1). initmode: Eout = I - s*D masked; else Eout = D.
//   Chain slots (slot >= nsq, 2 slots of 128 rows): yout = yin + Ech @ yin.
// =====================================================================================
__global__ __launch_bounds__(256, 2) void k_ns(
    const __nv_bfloat16* __restrict__ Esq, __nv_bfloat16* __restrict__ Eout,
    const __nv_bfloat16* __restrict__ Ech,
    const float* __restrict__ yin, float* __restrict__ yout,
    int nsq, int initmode) {
  __shared__ __align__(16) char smraw[41984];
  typedef __nv_bfloat16 (*TileP)[40];
  int tid = threadIdx.x, w = tid >> 5, lane = tid & 31;
  int gid = lane >> 2, tig = lane & 3;
  int bh = blockIdx.z, slot = blockIdx.x;
  size_t base = (size_t)bh * NSE;

  if (slot < nsq) {
    TileP sA0 = (TileP)(smraw);
    TileP sA1 = (TileP)(smraw + 10240);
    TileP sB0 = (TileP)(smraw + 20480);
    TileP sB1 = (TileP)(smraw + 30720);
    int m0 = (slot == 2) ? 128 : 0;
    int n0 = (slot >= 1) ? 128 : 0;
    int wm = w & 3, wn = w >> 2;
    const uint4* gE = (const uint4*)(Esq + base);
    float acc[2][8][4] = {};
    int r0 = tid >> 2, seg = tid & 3;
    cpa16(&sA0[r0][seg * 8],      gE + ((m0 + r0) * 32 + seg));
    cpa16(&sA0[r0 + 64][seg * 8], gE + ((m0 + r0 + 64) * 32 + seg));
    cpa16(&sB0[r0][seg * 8],      gE + ((n0 + r0) * 32 + seg));
    cpa16(&sB0[r0 + 64][seg * 8], gE + ((n0 + r0 + 64) * 32 + seg));
    CPA_COMMIT;
    for (int kc = 0; kc < 8; kc++) {
      TileP cA = (kc & 1) ? sA1 : sA0;
      TileP cB = (kc & 1) ? sB1 : sB0;
      if (kc < 7) {
        TileP nA = (kc & 1) ? sA0 : sA1;
        TileP nB = (kc & 1) ? sB0 : sB1;
        int kn = (kc + 1) * 4;
        cpa16(&nA[r0][seg * 8],      gE + ((m0 + r0) * 32 + kn + seg));
        cpa16(&nA[r0 + 64][seg * 8], gE + ((m0 + r0 + 64) * 32 + kn + seg));
        cpa16(&nB[r0][seg * 8],      gE + ((n0 + r0) * 32 + kn + seg));
        cpa16(&nB[r0 + 64][seg * 8], gE + ((n0 + r0 + 64) * 32 + kn + seg));
        CPA_COMMIT;
        CPA_WAIT1;
      } else {
        CPA_WAIT0;
      }
      __syncthreads();
      #pragma unroll
      for (int ks = 0; ks < 2; ks++) {
        int kb = ks * 16;
        uint32_t af[2][4], bf[8][2];
        #pragma unroll
        for (int mt = 0; mt < 2; mt++) {
          int row = wm * 32 + mt * 16 + gid;
          af[mt][0] = *(const uint32_t*)&cA[row][kb + tig * 2];
          af[mt][1] = *(const uint32_t*)&cA[row + 8][kb + tig * 2];
          af[mt][2] = *(const uint32_t*)&cA[row][kb + 8 + tig * 2];
          af[mt][3] = *(const uint32_t*)&cA[row + 8][kb + 8 + tig * 2];
        }
        #pragma unroll
        for (int nt = 0; nt < 8; nt++) {
          int brow = wn * 64 + nt * 8 + gid;
          bf[nt][0] = *(const uint32_t*)&cB[brow][kb + tig * 2];
          bf[nt][1] = *(const uint32_t*)&cB[brow][kb + 8 + tig * 2];
        }
        #pragma unroll
        for (int mt = 0; mt < 2; mt++)
          #pragma unroll
          for (int nt = 0; nt < 8; nt++)
            mma16816(acc[mt][nt], af[mt], bf[nt]);
      }
      __syncthreads();
    }
    float s = g_nsc[bh];
    __nv_bfloat16 (*tr)[129] = (__nv_bfloat16(*)[129])smraw;
    #pragma unroll
    for (int mt = 0; mt < 2; mt++) {
      #pragma unroll
      for (int nt = 0; nt < 8; nt++) {
        int row = m0 + wm * 32 + mt * 16 + gid;
        int col = n0 + wn * 64 + nt * 8 + tig * 2;
        #pragma unroll
        for (int half = 0; half < 2; half++) {
          int r = row + half * 8;
          float d0 = acc[mt][nt][half * 2], d1 = acc[mt][nt][half * 2 + 1];
          if (initmode) {
            d0 = (r < SM && col < SM) ? ((r == col ? 1.f : 0.f) - s * d0) : 0.f;
            d1 = (r < SM && col + 1 < SM) ? ((r == col + 1 ? 1.f : 0.f) - s * d1) : 0.f;
          }
          __nv_bfloat16 h0 = __float2bfloat16(d0), h1 = __float2bfloat16(d1);
          *(uint32_t*)(Eout + base + (size_t)r * NSP + col) = pack2(h0, h1);
          if (slot == 1) {
            int cl = col - 128;
            tr[r][cl] = h0;
            tr[r][cl + 1] = h1;
          }
        }
      }
    }
    if (slot == 1) {
      __syncthreads();
      #pragma unroll
      for (int i = 0; i < 16; i++) {
        int r2 = w * 16 + i;
        int j = lane * 4;
        uint2 pk;
        pk.x = pack2(tr[j][r2], tr[j + 1][r2]);
        pk.y = pack2(tr[j + 2][r2], tr[j + 3][r2]);
        *(uint2*)(Eout + base + (size_t)(128 + r2) * NSP + j) = pk;
      }
    }
  } else {
    // ---------------- chain role: yout = yin + Ech @ yin (128 rows per slot) ---------
    TileP sAc = (TileP)(smraw);
    __nv_bfloat16 (*sBy)[40] = (__nv_bfloat16(*)[40])(smraw + 10240);
    int cslot = slot - nsq;
    int m0c = cslot * 128;
    int wm = w & 3, wn = w >> 2;
    const uint4* gAc = (const uint4*)(Ech + base);
    const float* yb_in = yin + (size_t)bh * 256 * 64;
    float* yb_out = yout + (size_t)bh * 256 * 64;
    float acc[2][4][4] = {};
    int r0 = tid >> 2, seg = tid & 3;
    int kk = tid & 31, nb = (tid >> 5) * 8;
    for (int kc = 0; kc < 8; kc++) {
      *(uint4*)&sAc[r0][seg * 8]      = gAc[(m0c + r0) * 32 + kc * 4 + seg];
      *(uint4*)&sAc[r0 + 64][seg * 8] = gAc[(m0c + r0 + 64) * 32 + kc * 4 + seg];
      #pragma unroll
      for (int i = 0; i < 8; i++)
        sBy[nb + i][kk] = __float2bfloat16(yb_in[(size_t)(kc * 32 + kk) * 64 + nb + i]);
      __syncthreads();
      #pragma unroll
      for (int ks = 0; ks < 2; ks++) {
        int kb = ks * 16;
        uint32_t af[2][4], bf[4][2];
        #pragma unroll
        for (int mt = 0; mt < 2; mt++) {
          int row = wm * 32 + mt * 16 + gid;
          af[mt][0] = *(const uint32_t*)&sAc[row][kb + tig * 2];
          af[mt][1] = *(const uint32_t*)&sAc[row + 8][kb + tig * 2];
          af[mt][2] = *(const uint32_t*)&sAc[row][kb + 8 + tig * 2];
          af[mt][3] = *(const uint32_t*)&sAc[row + 8][kb + 8 + tig * 2];
        }
        #pragma unroll
        for (int nt = 0; nt < 4; nt++) {
          int brow = wn * 32 + nt * 8 + gid;
          bf[nt][0] = *(const uint32_t*)&sBy[brow][kb + tig * 2];
          bf[nt][1] = *(const uint32_t*)&sBy[brow][kb + 8 + tig * 2];
        }
        #pragma unroll
        for (int mt = 0; mt < 2; mt++)
          #pragma unroll
          for (int nt = 0; nt < 4; nt++)
            mma16816(acc[mt][nt], af[mt], bf[nt]);
      }
      __syncthreads();
    }
    #pragma unroll
    for (int mt = 0; mt < 2; mt++)
      #pragma unroll
      for (int half = 0; half < 2; half++) {
        int mr = m0c + wm * 32 + mt * 16 + gid + half * 8;
        #pragma unroll
        for (int nt = 0; nt < 4; nt++) {
          int col = wn * 32 + nt * 8 + tig * 2;
          yb_out[(size_t)mr * 64 + col] =
              yb_in[(size_t)mr * 64 + col] + acc[mt][nt][half * 2];
          yb_out[(size_t)mr * 64 + col + 1] =
              yb_in[(size_t)mr * 64 + col + 1] + acc[mt][nt][half * 2 + 1];
        }
      }
  }
}

// ---------------- k_fin: y20 = (I+E19) y19 ; Y = s * Pb @ y20. One CTA per bh. -------
__global__ __launch_bounds__(256) void k_fin(
    const __nv_bfloat16* __restrict__ E19, const __nv_bfloat16* __restrict__ Pb,
    const float* __restrict__ yin, float* __restrict__ ymid, float* __restrict__ yout) {
  __shared__ __align__(16) char smraw[15360];
  typedef __nv_bfloat16 (*TileP)[40];
  TileP sAc = (TileP)(smraw);
  __nv_bfloat16 (*sBy)[40] = (__nv_bfloat16(*)[40])(smraw + 10240);
  int tid = threadIdx.x, w = tid >> 5, lane = tid & 31;
  int gid = lane >> 2, tig = lane & 3;
  int wm = w & 3, wn = w >> 2;
  int bh = blockIdx.x;
  size_t base = (size_t)bh * NSE;
  float s = g_nsc[bh];
  int r0 = tid >> 2, seg = tid & 3;
  int kk = tid & 31, nb = (tid >> 5) * 8;
  #pragma unroll
  for (int st = 0; st < 2; st++) {
    const uint4* gAc = (const uint4*)((st ? Pb : E19) + base);
    const float* yi = (st ? ymid : yin) + (size_t)bh * 256 * 64;
    float* yo = (st ? yout : ymid) + (size_t)bh * 256 * 64;
    if (st) __syncthreads();
    #pragma unroll
    for (int pass = 0; pass < 2; pass++) {
      int m0c = pass * 128;
      float acc[2][4][4] = {};
      for (int kc = 0; kc < 8; kc++) {
        *(uint4*)&sAc[r0][seg * 8]      = gAc[(m0c + r0) * 32 + kc * 4 + seg];
        *(uint4*)&sAc[r0 + 64][seg * 8] = gAc[(m0c + r0 + 64) * 32 + kc * 4 + seg];
        #pragma unroll
        for (int i = 0; i < 8; i++)
          sBy[nb + i][kk] = __float2bfloat16(yi[(size_t)(kc * 32 + kk) * 64 + nb + i]);
        __syncthreads();
        #pragma unroll
        for (int ks = 0; ks < 2; ks++) {
          int kb = ks * 16;
          uint32_t af[2][4], bf[4][2];
          #pragma unroll
          for (int mt = 0; mt < 2; mt++) {
            int row = wm * 32 + mt * 16 + gid;
            af[mt][0] = *(const uint32_t*)&sAc[row][kb + tig * 2];
            af[mt][1] = *(const uint32_t*)&sAc[row + 8][kb + tig * 2];
            af[mt][2] = *(const uint32_t*)&sAc[row][kb + 8 + tig * 2];
            af[mt][3] = *(const uint32_t*)&sAc[row + 8][kb + 8 + tig * 2];
          }
          #pragma unroll
          for (int nt = 0; nt < 4; nt++) {
            int brow = wn * 32 + nt * 8 + gid;
            bf[nt][0] = *(const uint32_t*)&sBy[brow][kb + tig * 2];
            bf[nt][1] = *(const uint32_t*)&sBy[brow][kb + 8 + tig * 2];
          }
          #pragma unroll
          for (int mt = 0; mt < 2; mt++)
            #pragma unroll
            for (int nt = 0; nt < 4; nt++)
              mma16816(acc[mt][nt], af[mt], bf[nt]);
        }
        __syncthreads();
      }
      #pragma unroll
      for (int mt = 0; mt < 2; mt++)
        #pragma unroll
        for (int half = 0; half < 2; half++) {
          int mr = m0c + wm * 32 + mt * 16 + gid + half * 8;
          #pragma unroll
          for (int nt = 0; nt < 4; nt++) {
            int col = wn * 32 + nt * 8 + tig * 2;
            float d0 = acc[mt][nt][half * 2], d1 = acc[mt][nt][half * 2 + 1];
            float o0, o1;
            if (st) { o0 = s * d0; o1 = s * d1; }
            else {
              o0 = yi[(size_t)mr * 64 + col] + d0;
              o1 = yi[(size_t)mr * 64 + col + 1] + d1;
            }
            yo[(size_t)mr * 64 + col] = o0;
            yo[(size_t)mr * 64 + col + 1] = o1;
          }
        }
    }
  }
}

// ---------------- y0 += slice of Z = k1^T @ V (bf16 HMMA, K split over grid.x) --------
__global__ __launch_bounds__(256) void k_Zt(const float* __restrict__ V,
                                            float* __restrict__ y0) {
  __shared__ __align__(16) __nv_bfloat16 sA[128][40];   // [landmark][token]
  __shared__ __align__(16) __nv_bfloat16 sB[64][40];    // [channel][token]
  int tid = threadIdx.x, w = tid >> 5, lane = tid & 31;
  int gid = lane >> 2, tig = lane & 3;
  int wm = w & 3, wn = w >> 2;
  int bh = blockIdx.z, m0 = blockIdx.y * 128, kslice = blockIdx.x;
  const __nv_bfloat16* k1b = g_k1 + (size_t)bh * SN * SMP;
  const float* Vb = V + (size_t)bh * SN * 64;
  float acc[2][4][4] = {};
  int tokA = tid & 31, segA = tid >> 5;
  int cB = tid & 63, gB = tid >> 6;
  for (int kc = kslice * 14; kc < kslice * 14 + 14; kc++) {
    int k0 = kc * 32;
    const __nv_bfloat16* k1r = k1b + (size_t)(k0 + tokA) * SMP;
    #pragma unroll
    for (int i = 0; i < 4; i++) {
      int l = segA * 16 + i * 4;
      int gl = m0 + l;
      __align__(8) __nv_bfloat16 v4[4];
      if (gl + 3 < SMP) *(uint2*)v4 = *(const uint2*)&k1r[gl];
      else { v4[0] = v4[1] = v4[2] = v4[3] = __float2bfloat16(0.f); }
      sA[l][tokA] = v4[0]; sA[l + 1][tokA] = v4[1];
      sA[l + 2][tokA] = v4[2]; sA[l + 3][tokA] = v4[3];
    }
    #pragma unroll
    for (int i = 0; i < 8; i++) {
      int t = gB * 8 + i;
      sB[cB][t] = __float2bfloat16(Vb[(size_t)(k0 + t) * 64 + cB]);
    }
    __syncthreads();
    #pragma unroll
    for (int ks = 0; ks < 2; ks++) {
      int kb = ks * 16;
      uint32_t af[2][4], bf[4][2];
      #pragma unroll
      for (int mt = 0; mt < 2; mt++) {
        int row = wm * 32 + mt * 16 + gid;
        af[mt][0] = *(const uint32_t*)&sA[row][kb + tig * 2];
        af[mt][1] = *(const uint32_t*)&sA[row + 8][kb + tig * 2];
        af[mt][2] = *(const uint32_t*)&sA[row][kb + 8 + tig * 2];
        af[mt][3] = *(const uint32_t*)&sA[row + 8][kb + 8 + tig * 2];
      }
      #pragma unroll
      for (int nt = 0; nt < 4; nt++) {
        int brow = wn * 32 + nt * 8 + gid;
        bf[nt][0] = *(const uint32_t*)&sB[brow][kb + tig * 2];
        bf[nt][1] = *(const uint32_t*)&sB[brow][kb + 8 + tig * 2];
      }
      #pragma unroll
      for (int mt = 0; mt < 2; mt++)
        #pragma unroll
        for (int nt = 0; nt < 4; nt++)
          mma16816(acc[mt][nt], af[mt], bf[nt]);
    }
    __syncthreads();
  }
  float* yb = y0 + (size_t)bh * 256 * 64;
  #pragma unroll
  for (int mt = 0; mt < 2; mt++)
    #pragma unroll
    for (int half = 0; half < 2; half++) {
      int mr = m0 + wm * 32 + mt * 16 + gid + half * 8;
      #pragma unroll
      for (int nt = 0; nt < 4; nt++) {
        int n = wn * 32 + nt * 8 + tig * 2;
        atomicAdd(&yb[(size_t)mr * 64 + n],     acc[mt][nt][half * 2]);
        atomicAdd(&yb[(size_t)mr * 64 + n + 1], acc[mt][nt][half * 2 + 1]);
      }
    }
}

// ---------------- depthwise 3x3 conv residual -> d_out (smem-tiled strips) ----------
// Block: 4 output rows x 56 x 64ch for one bh; stages 6 input rows (86 KB smem).
__global__ __launch_bounds__(256) void k_conv(const float* __restrict__ V,
        const float* __restrict__ cw, float* __restrict__ out) {
  extern __shared__ float sV[];                  // [6][56*64] = 6*3584 floats
  int bh = blockIdx.y, h = bh & 7;
  int y0 = blockIdx.x * 4;
  int tid = threadIdx.x;
  const float* Vb = V + (size_t)bh * SN * 64;
  const float4* Vb4 = (const float4*)Vb;
  float4* sV4 = (float4*)sV;
  for (int i = tid; i < 6 * 896; i += 256) {
    int r = i / 896, rem = i - r * 896;
    int y = y0 - 1 + r;
    float4 v = make_float4(0.f, 0.f, 0.f, 0.f);
    if ((unsigned)y < SHW) v = Vb4[(size_t)y * 896 + rem];
    sV4[i] = v;
  }
  __syncthreads();
  float wgt[9];
  #pragma unroll
  for (int t = 0; t < 9; t++) wgt[t] = cw[t * 8 + h];
  float* ob = out + (size_t)bh * SN * 64;
  for (int j = tid; j < 4 * 3584; j += 256) {
    int lr = j / 3584;
    int pos = j - lr * 3584;
    int x = pos >> 6, c = pos & 63;
    float acc = 0.f;
    #pragma unroll
    for (int dy = 0; dy < 3; dy++)
      #pragma unroll
      for (int dx = -1; dx <= 1; dx++) {
        int xx = x + dx;
        if ((unsigned)xx < SHW)
          acc += wgt[dy * 3 + (dx + 1)] * sV[(lr + dy) * 3584 + xx * 64 + c];
      }
    int y = y0 + lr;
    ob[(size_t)(y * SHW + x) * 64 + c] = acc;
  }
}

// ---------------- out += k1 @ Y (bf16 HMMA, K=224 in 7 chunks) ----------------
__global__ __launch_bounds__(256) void k_Xt(const float* __restrict__ Yf,
                                            float* __restrict__ out) {
  __shared__ __align__(16) __nv_bfloat16 sA[128][40];
  __shared__ __align__(16) __nv_bfloat16 sB[64][40];
  int tid = threadIdx.x, w = tid >> 5, lane = tid & 31;
  int gid = lane >> 2, tig = lane & 3;
  int wm = w & 3, wn = w >> 2;
  int bh = blockIdx.z, m0 = blockIdx.y * 128;
  const __nv_bfloat16* k1b = g_k1 + (size_t)bh * SN * SMP;
  const float* Yb = Yf + (size_t)bh * 256 * 64;
  float acc[2][4][4] = {};
  int r0 = tid >> 2, seg = tid & 3;
  int cB = tid & 63, gB = tid >> 6;
  for (int kc = 0; kc < 7; kc++) {
    int k0 = kc * 32;
    #pragma unroll
    for (int rr = 0; rr < 2; rr++) {
      int gm = m0 + r0 + rr * 64;
      uint4 v = make_uint4(0, 0, 0, 0);
      if (gm < SN) v = *(const uint4*)&k1b[(size_t)gm * SMP + k0 + seg * 8];
      *(uint4*)&sA[r0 + rr * 64][seg * 8] = v;
    }
    #pragma unroll
    for (int i = 0; i < 8; i++) {
      int t = gB * 8 + i;
      sB[cB][t] = __float2bfloat16(Yb[(size_t)(k0 + t) * 64 + cB]);
    }
    __syncthreads();
    #pragma unroll
    for (int ks = 0; ks < 2; ks++) {
      int kb = ks * 16;
      uint32_t af[2][4], bf[4][2];
      #pragma unroll
      for (int mt = 0; mt < 2; mt++) {
        int row = wm * 32 + mt * 16 + gid;
        af[mt][0] = *(const uint32_t*)&sA[row][kb + tig * 2];
        af[mt][1] = *(const uint32_t*)&sA[row + 8][kb + tig * 2];
        af[mt][2] = *(const uint32_t*)&sA[row][kb + 8 + tig * 2];
        af[mt][3] = *(const uint32_t*)&sA[row + 8][kb + 8 + tig * 2];
      }
      #pragma unroll
      for (int nt = 0; nt < 4; nt++) {
        int brow = wn * 32 + nt * 8 + gid;
        bf[nt][0] = *(const uint32_t*)&sB[brow][kb + tig * 2];
        bf[nt][1] = *(const uint32_t*)&sB[brow][kb + 8 + tig * 2];
      }
      #pragma unroll
      for (int mt = 0; mt < 2; mt++)
        #pragma unroll
        for (int nt = 0; nt < 4; nt++)
          mma16816(acc[mt][nt], af[mt], bf[nt]);
    }
    __syncthreads();
  }
  float* ob = out + (size_t)bh * SN * 64;
  #pragma unroll
  for (int mt = 0; mt < 2; mt++)
    #pragma unroll
    for (int half = 0; half < 2; half++) {
      int mr = m0 + wm * 32 + mt * 16 + gid + half * 8;
      if (mr >= SN) continue;
      #pragma unroll
      for (int nt = 0; nt < 4; nt++) {
        int n = wn * 32 + nt * 8 + tig * 2;
        ob[(size_t)mr * 64 + n]     += acc[mt][nt][half * 2];
        ob[(size_t)mr * 64 + n + 1] += acc[mt][nt][half * 2 + 1];
      }
    }
}

// ---------------- host launch ----------------
extern "C" void kernel_launch(void* const* d_in, const int* in_sizes, int n_in,
                              void* d_out, int out_size) {
  const float* Q     = (const float*)d_in[0];
  const float* V     = (const float*)d_in[1];
  const float* wl    = (const float*)d_in[2];
  const float* gamma = (const float*)d_in[3];
  const float* beta  = (const float*)d_in[4];
  const float* cw    = (const float*)d_in[5];
  float* out = (float*)d_out;

  float *pQl, *pql2, *pqn2, *py0, *py1;
  cudaGetSymbolAddress((void**)&pQl,  g_Ql);
  cudaGetSymbolAddress((void**)&pql2, g_ql2);
  cudaGetSymbolAddress((void**)&pqn2, g_qn2);
  cudaGetSymbolAddress((void**)&py0,  g_y0);
  cudaGetSymbolAddress((void**)&py1,  g_y1);
  __nv_bfloat16 *pEa, *pEb, *pPb;
  cudaGetSymbolAddress((void**)&pPb, g_Pb);
  cudaGetSymbolAddress((void**)&pEa, g_Ea);
  cudaGetSymbolAddress((void**)&pEb, g_Eb);

  const int CONV_SMEM = 6 * 3584 * 4;   // 86016
  cudaFuncSetAttribute(k_conv, cudaFuncAttributeMaxDynamicSharedMemorySize, CONV_SMEM);

  // landmarks, P, scale (+zero y0), NS init
  k_land<<<dim3(1, 2, SBH), 256>>>(Q, wl, gamma, beta);
  k_gs<<<dim3(2, 2, SBH), 256>>>(pQl, pql2, SM, 1.f, 1);
  k_scale<<<SBH, 256>>>();
  k_ns<<<dim3(3, 1, SBH), 256>>>(pPb, pEa, nullptr, nullptr, nullptr, 3, 1);
  // k1 path (independent of NS)
  k_qn2<<<dim3(SN / 8, SBH), 256>>>(Q);
  k_gs<<<dim3(2, 25, SBH), 256>>>(Q, pqn2, SN, QS, 0);
  k_Zt<<<dim3(7, 2, SBH), 256>>>(V, py0);
  // 19 merged steps: E_{k+1}=E_k^2 (3 slots) + y_{k+1}=(I+E_k)y_k (2 slots)
  __nv_bfloat16 *ec = pEa, *en = pEb;
  float *yc = py0, *yn = py1;
  for (int k = 0; k < 19; k++) {
    k_ns<<<dim3(5, 1, SBH), 256>>>(ec, en, ec, yc, yn, 3, 0);
    __nv_bfloat16* te = ec; ec = en; en = te;
    float* ty = yc; yc = yn; yn = ty;
  }
  // y20 = (I+E19) y19 ; Y = s * Pb @ y20   (single fused launch)
  k_fin<<<SBH, 256>>>(ec, pPb, yc, yn, yc);
  // conv residual -> out (smem-tiled), then out += k1 @ Y
  k_conv<<<dim3(14, SBH), 256, CONV_SMEM>>>(V, cw, out);
  k_Xt<<<dim3(1, 25, SBH), 256>>>(yc, out);
}